// round 1
// baseline (speedup 1.0000x reference)
#include <cuda_runtime.h>
#include <cuda_bf16.h>
#include <math.h>

#define B_    32
#define C_    64
#define F_    4096
#define N_    (B_ * F_)          // 131072 tokens
#define SIZE_ 2048
#define DECAY_ 0.99f
#define OMD_   0.01f             // 1 - decay
#define EPS_   1e-5f

// ---- output layout (concatenated tuple, all float32) ----
#define OFF_Q     0
#define OFF_IDX   8388608
#define OFF_LOSS  8519680
#define OFF_NEMB  8519681
#define OFF_NCS   8650753
#define OFF_NEA   8652801
// total = 8783873

// ---- device scratch (no allocations allowed) ----
__device__ float g_ET[C_ * SIZE_];        // E^T: [c][code]
__device__ float g_e2h[SIZE_];            // 0.5 * ||e||^2
__device__ int   g_idx[N_];
__device__ float g_emb_sum[SIZE_ * C_];
__device__ float g_cs[SIZE_];
__device__ float g_inv[SIZE_];            // 1 / smoothed
__device__ float g_loss;

// ============================================================
// Kernel 0: transpose codebook, compute 0.5||e||^2, zero scratch
// grid 512 x 256 = 131072 threads
// ============================================================
__global__ void k_init(const float* __restrict__ embedding) {
    int i = blockIdx.x * blockDim.x + threadIdx.x;   // 0 .. 131071
    int code = i >> 6;
    int c    = i & 63;
    g_ET[c * SIZE_ + code] = embedding[i];
    g_emb_sum[i] = 0.0f;
    if (i < SIZE_) {
        const float* e = embedding + i * C_;
        float s = 0.0f;
#pragma unroll
        for (int k = 0; k < C_; k++) s += e[k] * e[k];
        g_e2h[i] = 0.5f * s;
        g_cs[i] = 0.0f;
    }
    if (i == 0) g_loss = 0.0f;
}

// ============================================================
// Kernel 1: argmin over codes.  score = 0.5||e||^2 - x.e
// Block = 128 tokens (one batch b, 128 consecutive f).
// 256 threads = 16(tx: codes) x 16(ty: tokens); 8x8 microtile.
// Loops over 16 chunks of 128 codes; running argmin kept in regs
// of the tx==0 threads.
// dynamic smem: As[64][128] | Bs[64][128] | e2s[128]
// ============================================================
__global__ void __launch_bounds__(256)
k_argmin(const float* __restrict__ inputs) {
    extern __shared__ float smem[];
    float* As = smem;                 // 8192 floats
    float* Bs = smem + 8192;          // 8192 floats
    float* e2s = smem + 16384;        // 128 floats
    float4* As4 = (float4*)As;
    float4* Bs4 = (float4*)Bs;

    int tid = threadIdx.x;
    int tx = tid & 15;       // code group
    int ty = tid >> 4;       // token group
    int b  = blockIdx.x >> 5;
    int f0 = (blockIdx.x & 31) << 7;

    // load A tile: As[k][m] = inputs[b][k][f0+m]   (k = channel)
    const float4* inp4 = (const float4*)(inputs + (size_t)b * C_ * F_);
    int f04 = f0 >> 2;
#pragma unroll
    for (int it = tid; it < 2048; it += 256) {
        int k = it >> 5, m4 = it & 31;
        As4[it] = inp4[k * (F_ / 4) + f04 + m4];
    }

    float bv[8];
    int   bi[8];
#pragma unroll
    for (int i = 0; i < 8; i++) { bv[i] = 3.4e38f; bi[i] = 0; }

#pragma unroll 1
    for (int chunk = 0; chunk < 16; chunk++) {
        int cbase = chunk << 7;
        __syncthreads();
        // load B tile: Bs[k][n] = ET[k][cbase+n]
        int cb4 = cbase >> 2;
#pragma unroll
        for (int it = tid; it < 2048; it += 256) {
            int k = it >> 5, n4 = it & 31;
            Bs4[it] = ((const float4*)g_ET)[k * (SIZE_ / 4) + cb4 + n4];
        }
        if (tid < 128) e2s[tid] = g_e2h[cbase + tid];
        __syncthreads();

        float acc[8][8];
#pragma unroll
        for (int i = 0; i < 8; i++)
#pragma unroll
            for (int j = 0; j < 8; j++) acc[i][j] = 0.0f;

#pragma unroll 8
        for (int k = 0; k < 64; k++) {
            float4 a0 = As4[k * 32 + ty * 2];
            float4 a1 = As4[k * 32 + ty * 2 + 1];
            float4 b0 = Bs4[k * 32 + tx * 2];
            float4 b1 = Bs4[k * 32 + tx * 2 + 1];
            float av[8] = {a0.x, a0.y, a0.z, a0.w, a1.x, a1.y, a1.z, a1.w};
            float bw[8] = {b0.x, b0.y, b0.z, b0.w, b1.x, b1.y, b1.z, b1.w};
#pragma unroll
            for (int i = 0; i < 8; i++)
#pragma unroll
                for (int j = 0; j < 8; j++)
                    acc[i][j] = fmaf(av[i], bw[j], acc[i][j]);
        }

        // per-token argmin: local over 8 codes, then across 16 tx lanes
#pragma unroll
        for (int i = 0; i < 8; i++) {
            float v = e2s[tx * 8] - acc[i][0];
            int   ci = cbase + tx * 8;
#pragma unroll
            for (int j = 1; j < 8; j++) {
                float w = e2s[tx * 8 + j] - acc[i][j];
                if (w < v) { v = w; ci = cbase + tx * 8 + j; }
            }
#pragma unroll
            for (int off = 8; off > 0; off >>= 1) {
                float ov = __shfl_down_sync(0xffffffffu, v, off, 16);
                int   oi = __shfl_down_sync(0xffffffffu, ci, off, 16);
                if (ov < v || (ov == v && oi < ci)) { v = ov; ci = oi; }
            }
            if (tx == 0) {
                if (v < bv[i] || (v == bv[i] && ci < bi[i])) { bv[i] = v; bi[i] = ci; }
            }
        }
    }

    if (tx == 0) {
        int tbase = b * F_ + f0 + ty * 8;
#pragma unroll
        for (int i = 0; i < 8; i++) g_idx[tbase + i] = bi[i];
    }
}

// ============================================================
// Kernel 2: gather quantized + write output tile, scatter segment
// sums (atomics), commitment loss.  Block = 128 tokens, 128 thr.
// ============================================================
__global__ void __launch_bounds__(128)
k_scatter(const float* __restrict__ inputs,
          const float* __restrict__ embedding,
          float* __restrict__ out) {
    __shared__ float xs[C_ * 128];   // [c][m], 32KB (x in, then q)
    float4* xs4 = (float4*)xs;

    int tid = threadIdx.x;
    int b  = blockIdx.x >> 5;
    int f0 = (blockIdx.x & 31) << 7;

    const float4* inp4 = (const float4*)(inputs + (size_t)b * C_ * F_);
    int f04 = f0 >> 2;
#pragma unroll
    for (int it = tid; it < 2048; it += 128) {
        int k = it >> 5, m4 = it & 31;
        xs4[it] = inp4[k * (F_ / 4) + f04 + m4];
    }
    __syncthreads();

    int t = b * F_ + f0 + tid;
    int idx = g_idx[t];
    const float4* e4 = (const float4*)(embedding + idx * C_);
    float* esum = g_emb_sum + (size_t)idx * C_;

    float lacc = 0.0f;
#pragma unroll
    for (int c4 = 0; c4 < 16; c4++) {
        float4 q = e4[c4];
        float qv[4] = {q.x, q.y, q.z, q.w};
#pragma unroll
        for (int l = 0; l < 4; l++) {
            int c = c4 * 4 + l;
            float x = xs[c * 128 + tid];
            float d = x - qv[l];
            lacc = fmaf(d, d, lacc);
            atomicAdd(&esum[c], x);
            xs[c * 128 + tid] = qv[l];
        }
    }
    atomicAdd(&g_cs[idx], 1.0f);
    out[OFF_IDX + t] = (float)idx;

    // loss warp reduce
#pragma unroll
    for (int off = 16; off > 0; off >>= 1)
        lacc += __shfl_down_sync(0xffffffffu, lacc, off);
    if ((tid & 31) == 0) atomicAdd(&g_loss, lacc);

    __syncthreads();
    // write quantized tile [b][c][f0..f0+128) coalesced
    float4* out4 = (float4*)(out + OFF_Q);
    size_t rowbase = (size_t)b * C_ * F_;
#pragma unroll
    for (int it = tid; it < 2048; it += 128) {
        int c = it >> 5, m4 = it & 31;
        out4[(rowbase + (size_t)c * F_ + f0) / 4 + m4] = xs4[it];
    }
}

// ============================================================
// Kernel 3: new_cluster_size, n, 1/smoothed, loss.  1 block.
// ============================================================
__global__ void __launch_bounds__(1024)
k_ema1(const float* __restrict__ cluster_size, float* __restrict__ out) {
    __shared__ float wsum[32];
    __shared__ float s_n;
    int tid = threadIdx.x;

    float ncs0 = DECAY_ * cluster_size[tid] + OMD_ * g_cs[tid];
    float ncs1 = DECAY_ * cluster_size[tid + 1024] + OMD_ * g_cs[tid + 1024];
    out[OFF_NCS + tid] = ncs0;
    out[OFF_NCS + tid + 1024] = ncs1;

    float s = ncs0 + ncs1;
#pragma unroll
    for (int off = 16; off > 0; off >>= 1)
        s += __shfl_down_sync(0xffffffffu, s, off);
    if ((tid & 31) == 0) wsum[tid >> 5] = s;
    __syncthreads();
    if (tid == 0) {
        float n = 0.0f;
#pragma unroll
        for (int w = 0; w < 32; w++) n += wsum[w];
        s_n = n;
        out[OFF_LOSS] = g_loss * (1.0f / (float)(N_ * C_));
    }
    __syncthreads();
    float n = s_n;
    float denom = n + (float)SIZE_ * EPS_;
    float mn = fmaxf(n, 1.0f);
    g_inv[tid]        = denom / ((ncs0 + EPS_) * mn);
    g_inv[tid + 1024] = denom / ((ncs1 + EPS_) * mn);
}

// ============================================================
// Kernel 4: new_embedding_avg and new_embedding.
// ============================================================
__global__ void __launch_bounds__(256)
k_ema2(const float* __restrict__ embedding_avg, float* __restrict__ out) {
    int i = blockIdx.x * 256 + threadIdx.x;   // 0 .. 131071
    int row = i >> 6;
    float nea = DECAY_ * embedding_avg[i] + OMD_ * g_emb_sum[i];
    out[OFF_NEA + i]  = nea;
    out[OFF_NEMB + i] = nea * g_inv[row];
}

// ============================================================
extern "C" void kernel_launch(void* const* d_in, const int* in_sizes, int n_in,
                              void* d_out, int out_size) {
    const float* inputs        = (const float*)d_in[0];
    const float* embedding     = (const float*)d_in[1];
    const float* embedding_avg = (const float*)d_in[2];
    const float* cluster_size  = (const float*)d_in[3];
    float* out = (float*)d_out;

    cudaFuncSetAttribute(k_argmin, cudaFuncAttributeMaxDynamicSharedMemorySize, 66048);

    k_init<<<512, 256>>>(embedding);
    k_argmin<<<1024, 256, 66048>>>(inputs);
    k_scatter<<<1024, 128>>>(inputs, embedding, out);
    k_ema1<<<1, 1024>>>(cluster_size, out);
    k_ema2<<<512, 256>>>(embedding_avg, out);
}

// round 3
// speedup vs baseline: 1.9708x; 1.9708x over previous
#include <cuda_runtime.h>
#include <cuda_fp16.h>
#include <math.h>
#include <stdint.h>

#define B_    32
#define C_    64
#define F_    4096
#define N_    (B_ * F_)          // 131072 tokens
#define SIZE_ 2048
#define DECAY_ 0.99f
#define OMD_   0.01f
#define EPS_   1e-5f

// ---- output layout (concatenated tuple, all float32) ----
#define OFF_Q     0
#define OFF_IDX   8388608
#define OFF_LOSS  8519680
#define OFF_NEMB  8519681
#define OFF_NCS   8650753
#define OFF_NEA   8652801

// ---- device scratch ----
// codebook, fp16 hi/lo interleaved per k-pair: [code][32 pairs][2 u32]
__device__ uint32_t g_B16[SIZE_ * 64];
__device__ float g_e2h[SIZE_];       // 0.5 * ||e||^2 (fp32)
__device__ int   g_idx[N_];
__device__ float g_emb_sum[SIZE_ * C_];
__device__ float g_cs[SIZE_];
__device__ float g_inv[SIZE_];
__device__ float g_loss;

// ---- smem layout for the GEMM kernel (byte offsets) ----
#define SM_A    0                 // A fp16 hi/lo interleaved: 128 m x 288B
#define SM_B0   36864             // B chunk buf 0: 128 codes x 288B
#define SM_B1   73728             // B chunk buf 1
#define SM_E2   110592            // 2048 f32 = 8192 B
#define SM_TOT  118784
// raw fp32 input slab (64c x 128f = 32KB) is staged in SM_B0 before B loads

__device__ __forceinline__ uint32_t smem_u32(const void* p) {
    uint32_t a;
    asm("{ .reg .u64 t; cvta.to.shared.u64 t, %1; cvt.u32.u64 %0, t; }"
        : "=r"(a) : "l"(p));
    return a;
}

__device__ __forceinline__ void cp_async16(uint32_t dst, const void* src) {
    asm volatile("cp.async.ca.shared.global [%0], [%1], 16;"
                 :: "r"(dst), "l"(src) : "memory");
}
#define CP_COMMIT() asm volatile("cp.async.commit_group;" ::: "memory")
#define CP_WAIT1()  asm volatile("cp.async.wait_group 1;"  ::: "memory")
#define CP_WAIT0()  asm volatile("cp.async.wait_group 0;"  ::: "memory")

__device__ __forceinline__ void mma16816(float c[4],
                                         uint32_t a0, uint32_t a1, uint32_t a2, uint32_t a3,
                                         uint32_t b0, uint32_t b1) {
    asm volatile(
        "mma.sync.aligned.m16n8k16.row.col.f32.f16.f16.f32 "
        "{%0,%1,%2,%3}, {%4,%5,%6,%7}, {%8,%9}, {%0,%1,%2,%3};"
        : "+f"(c[0]), "+f"(c[1]), "+f"(c[2]), "+f"(c[3])
        : "r"(a0), "r"(a1), "r"(a2), "r"(a3), "r"(b0), "r"(b1));
}

// ============================================================
// Kernel 0: codebook fp16 hi/lo split + 0.5||e||^2 + zero scratch
// ============================================================
__global__ void k_init(const float* __restrict__ embedding) {
    int i = blockIdx.x * blockDim.x + threadIdx.x;   // 0..131071
    int code = i >> 6;
    int c    = i & 63;
    if ((c & 1) == 0) {
        float e0 = embedding[i];
        float e1 = embedding[i + 1];
        __half h0 = __float2half_rn(e0);
        __half h1 = __float2half_rn(e1);
        __half l0 = __float2half_rn(e0 - __half2float(h0));
        __half l1 = __float2half_rn(e1 - __half2float(h1));
        __half2 hi = __halves2half2(h0, h1);   // low half = k even
        __half2 lo = __halves2half2(l0, l1);
        int pr = c >> 1;
        g_B16[code * 64 + pr * 2]     = *(uint32_t*)&hi;
        g_B16[code * 64 + pr * 2 + 1] = *(uint32_t*)&lo;
    }
    g_emb_sum[i] = 0.0f;
    if (i < SIZE_) {
        const float* er = embedding + i * C_;
        float s = 0.0f;
#pragma unroll
        for (int k = 0; k < C_; k++) s += er[k] * er[k];
        g_e2h[i] = 0.5f * s;
        g_cs[i] = 0.0f;
    }
    if (i == 0) g_loss = 0.0f;
}

// ============================================================
// Kernel 1: split-fp16 mma.sync distance GEMM + fused argmin
// CTA = 128 tokens, 256 threads (8 warps x 16 tokens).
// 16 chunks of 128 codes, cp.async double-buffered.
// ============================================================
__global__ void __launch_bounds__(256, 1)
k_argmin_mma(const float* __restrict__ inputs) {
    extern __shared__ char sm[];
    uint32_t smb = smem_u32(sm);

    int tid = threadIdx.x;
    int w    = tid >> 5;
    int lane = tid & 31;
    int gid  = lane >> 2;
    int tig  = lane & 3;
    int b  = blockIdx.x >> 5;
    int f0 = (blockIdx.x & 31) << 7;

    // ---- stage raw fp32 slab [64 c][128 f] into SM_B0 (coalesced) ----
    {
        const float4* inp4 = (const float4*)(inputs + (size_t)b * C_ * F_ + f0);
        float4* raw4 = (float4*)(sm + SM_B0);
#pragma unroll
        for (int it = tid; it < 2048; it += 256) {
            int c = it >> 5, m4 = it & 31;
            raw4[it] = inp4[c * (F_ / 4) + m4];
        }
    }
    // e2 table
    {
        const float4* src = (const float4*)g_e2h;
        float4* dst = (float4*)(sm + SM_E2);
#pragma unroll
        for (int it = tid; it < 512; it += 256) dst[it] = src[it];
    }
    __syncthreads();

    // ---- convert slab -> A fp16 hi/lo interleaved [m][pair][hi,lo] ----
    {
        const float* raw = (const float*)(sm + SM_B0);
#pragma unroll
        for (int it = tid; it < 4096; it += 256) {   // 128 m x 32 pairs
            int m = it & 127, j = it >> 7;
            float x0 = raw[(2 * j)     * 128 + m];
            float x1 = raw[(2 * j + 1) * 128 + m];
            __half h0 = __float2half_rn(x0);
            __half h1 = __float2half_rn(x1);
            __half l0 = __float2half_rn(x0 - __half2float(h0));
            __half l1 = __float2half_rn(x1 - __half2float(h1));
            __half2 hi = __halves2half2(h0, h1);
            __half2 lo = __halves2half2(l0, l1);
            uint2 v = {*(uint32_t*)&hi, *(uint32_t*)&lo};
            *(uint2*)(sm + SM_A + m * 288 + j * 8) = v;
        }
    }
    __syncthreads();

    // ---- load A fragments to registers (kept whole kernel) ----
    uint32_t ah[16], al[16];
#pragma unroll
    for (int s = 0; s < 4; s++) {
#pragma unroll
        for (int part = 0; part < 4; part++) {
            int m  = 16 * w + gid + (part & 1) * 8;
            int pr = 8 * s + tig + (part >> 1) * 4;
            uint2 v = *(const uint2*)(sm + SM_A + m * 288 + pr * 8);
            ah[s * 4 + part] = v.x;
            al[s * 4 + part] = v.y;
        }
    }
    __syncthreads();   // SM_B0 raw slab now dead

    // ---- prologue: cp.async B chunk 0 and 1 ----
    const char* gB = (const char*)g_B16;
#pragma unroll
    for (int r = 0; r < 8; r++) {
        int o = tid + 256 * r;            // 0..2047
        int row = o >> 4, g = o & 15;
        cp_async16(smb + SM_B0 + row * 288 + g * 16,
                   gB + (size_t)row * 256 + g * 16);
    }
    CP_COMMIT();
#pragma unroll
    for (int r = 0; r < 8; r++) {
        int o = tid + 256 * r;
        int row = o >> 4, g = o & 15;
        cp_async16(smb + SM_B1 + row * 288 + g * 16,
                   gB + (size_t)(128 + row) * 256 + g * 16);
    }
    CP_COMMIT();

    float bestv0 = 3.4e38f, bestv1 = 3.4e38f;
    int   besti0 = 0,       besti1 = 0;

#pragma unroll 1
    for (int i = 0; i < 16; i++) {
        if (i < 14) { CP_WAIT1(); } else { CP_WAIT0(); }
        __syncthreads();
        const char* buf = sm + ((i & 1) ? SM_B1 : SM_B0);

#pragma unroll
        for (int nt = 0; nt < 16; nt++) {
            int n = nt * 8 + gid;
            const char* base = buf + n * 288;
            uint32_t bh[8], bl[8];
#pragma unroll
            for (int s = 0; s < 4; s++) {
                uint2 v0 = *(const uint2*)(base + (8 * s + tig) * 8);
                uint2 v1 = *(const uint2*)(base + (8 * s + tig + 4) * 8);
                bh[s * 2]     = v0.x;  bl[s * 2]     = v0.y;
                bh[s * 2 + 1] = v1.x;  bl[s * 2 + 1] = v1.y;
            }
            float c[4] = {0.f, 0.f, 0.f, 0.f};
#pragma unroll
            for (int s = 0; s < 4; s++)   // hh
                mma16816(c, ah[4*s], ah[4*s+1], ah[4*s+2], ah[4*s+3], bh[2*s], bh[2*s+1]);
#pragma unroll
            for (int s = 0; s < 4; s++)   // hl
                mma16816(c, ah[4*s], ah[4*s+1], ah[4*s+2], ah[4*s+3], bl[2*s], bl[2*s+1]);
#pragma unroll
            for (int s = 0; s < 4; s++)   // lh
                mma16816(c, al[4*s], al[4*s+1], al[4*s+2], al[4*s+3], bh[2*s], bh[2*s+1]);

            int col = i * 128 + nt * 8 + 2 * tig;
            float2 e2v = *(const float2*)(sm + SM_E2 + col * 4);
            float s0 = e2v.x - c[0];
            float s1 = e2v.y - c[1];
            float s2 = e2v.x - c[2];
            float s3 = e2v.y - c[3];
            if (s0 < bestv0) { bestv0 = s0; besti0 = col; }
            if (s1 < bestv0) { bestv0 = s1; besti0 = col + 1; }
            if (s2 < bestv1) { bestv1 = s2; besti1 = col; }
            if (s3 < bestv1) { bestv1 = s3; besti1 = col + 1; }
        }
        __syncthreads();
        if (i < 14) {   // issue chunk i+2 into buf (i&1)
            uint32_t dstb = smb + ((i & 1) ? SM_B1 : SM_B0);
            size_t srcb = (size_t)(i + 2) * 128 * 256;
#pragma unroll
            for (int r = 0; r < 8; r++) {
                int o = tid + 256 * r;
                int row = o >> 4, g = o & 15;
                cp_async16(dstb + row * 288 + g * 16,
                           gB + srcb + (size_t)row * 256 + g * 16);
            }
            CP_COMMIT();
        }
    }

    // ---- cross-lane (quad) argmin reduce, then store ----
#pragma unroll
    for (int off = 1; off <= 2; off <<= 1) {
        float ov0 = __shfl_xor_sync(0xffffffffu, bestv0, off);
        int   oi0 = __shfl_xor_sync(0xffffffffu, besti0, off);
        float ov1 = __shfl_xor_sync(0xffffffffu, bestv1, off);
        int   oi1 = __shfl_xor_sync(0xffffffffu, besti1, off);
        if (ov0 < bestv0 || (ov0 == bestv0 && oi0 < besti0)) { bestv0 = ov0; besti0 = oi0; }
        if (ov1 < bestv1 || (ov1 == bestv1 && oi1 < besti1)) { bestv1 = ov1; besti1 = oi1; }
    }
    if (tig == 0) {
        int tok = b * F_ + f0 + w * 16 + gid;
        g_idx[tok]     = besti0;
        g_idx[tok + 8] = besti1;
    }
}

// ============================================================
// Kernel 2: gather quantized + scatter segment sums + loss
// ============================================================
__global__ void __launch_bounds__(128)
k_scatter(const float* __restrict__ inputs,
          const float* __restrict__ embedding,
          float* __restrict__ out) {
    __shared__ float xs[C_ * 128];
    float4* xs4 = (float4*)xs;

    int tid = threadIdx.x;
    int b  = blockIdx.x >> 5;
    int f0 = (blockIdx.x & 31) << 7;

    const float4* inp4 = (const float4*)(inputs + (size_t)b * C_ * F_);
    int f04 = f0 >> 2;
#pragma unroll
    for (int it = tid; it < 2048; it += 128) {
        int k = it >> 5, m4 = it & 31;
        xs4[it] = inp4[k * (F_ / 4) + f04 + m4];
    }
    __syncthreads();

    int t = b * F_ + f0 + tid;
    int idx = g_idx[t];
    const float4* e4 = (const float4*)(embedding + idx * C_);
    float* esum = g_emb_sum + (size_t)idx * C_;

    float lacc = 0.0f;
#pragma unroll
    for (int c4 = 0; c4 < 16; c4++) {
        float4 q = e4[c4];
        float qv[4] = {q.x, q.y, q.z, q.w};
#pragma unroll
        for (int l = 0; l < 4; l++) {
            int c = c4 * 4 + l;
            float x = xs[c * 128 + tid];
            float d = x - qv[l];
            lacc = fmaf(d, d, lacc);
            atomicAdd(&esum[c], x);
            xs[c * 128 + tid] = qv[l];
        }
    }
    atomicAdd(&g_cs[idx], 1.0f);
    out[OFF_IDX + t] = (float)idx;

#pragma unroll
    for (int off = 16; off > 0; off >>= 1)
        lacc += __shfl_down_sync(0xffffffffu, lacc, off);
    if ((tid & 31) == 0) atomicAdd(&g_loss, lacc);

    __syncthreads();
    float4* out4 = (float4*)(out + OFF_Q);
    size_t rowbase = (size_t)b * C_ * F_;
#pragma unroll
    for (int it = tid; it < 2048; it += 128) {
        int c = it >> 5, m4 = it & 31;
        out4[(rowbase + (size_t)c * F_ + f0) / 4 + m4] = xs4[it];
    }
}

// ============================================================
// Kernel 3: new_cluster_size, n, 1/smoothed, loss.  1 block.
// ============================================================
__global__ void __launch_bounds__(1024)
k_ema1(const float* __restrict__ cluster_size, float* __restrict__ out) {
    __shared__ float wsum[32];
    __shared__ float s_n;
    int tid = threadIdx.x;

    float ncs0 = DECAY_ * cluster_size[tid] + OMD_ * g_cs[tid];
    float ncs1 = DECAY_ * cluster_size[tid + 1024] + OMD_ * g_cs[tid + 1024];
    out[OFF_NCS + tid] = ncs0;
    out[OFF_NCS + tid + 1024] = ncs1;

    float s = ncs0 + ncs1;
#pragma unroll
    for (int off = 16; off > 0; off >>= 1)
        s += __shfl_down_sync(0xffffffffu, s, off);
    if ((tid & 31) == 0) wsum[tid >> 5] = s;
    __syncthreads();
    if (tid == 0) {
        float n = 0.0f;
#pragma unroll
        for (int w = 0; w < 32; w++) n += wsum[w];
        s_n = n;
        out[OFF_LOSS] = g_loss * (1.0f / (float)(N_ * C_));
    }
    __syncthreads();
    float n = s_n;
    float denom = n + (float)SIZE_ * EPS_;
    float mn = fmaxf(n, 1.0f);
    g_inv[tid]        = denom / ((ncs0 + EPS_) * mn);
    g_inv[tid + 1024] = denom / ((ncs1 + EPS_) * mn);
}

// ============================================================
// Kernel 4: new_embedding_avg and new_embedding.
// ============================================================
__global__ void __launch_bounds__(256)
k_ema2(const float* __restrict__ embedding_avg, float* __restrict__ out) {
    int i = blockIdx.x * 256 + threadIdx.x;
    int row = i >> 6;
    float nea = DECAY_ * embedding_avg[i] + OMD_ * g_emb_sum[i];
    out[OFF_NEA + i]  = nea;
    out[OFF_NEMB + i] = nea * g_inv[row];
}

// ============================================================
extern "C" void kernel_launch(void* const* d_in, const int* in_sizes, int n_in,
                              void* d_out, int out_size) {
    const float* inputs        = (const float*)d_in[0];
    const float* embedding     = (const float*)d_in[1];
    const float* embedding_avg = (const float*)d_in[2];
    const float* cluster_size  = (const float*)d_in[3];
    float* out = (float*)d_out;

    cudaFuncSetAttribute(k_argmin_mma, cudaFuncAttributeMaxDynamicSharedMemorySize, SM_TOT);

    k_init<<<512, 256>>>(embedding);
    k_argmin_mma<<<1024, 256, SM_TOT>>>(inputs);
    k_scatter<<<1024, 128>>>(inputs, embedding, out);
    k_ema1<<<1, 1024>>>(cluster_size, out);
    k_ema2<<<512, 256>>>(embedding_avg, out);
}

// round 4
// speedup vs baseline: 2.1103x; 1.0708x over previous
#include <cuda_runtime.h>
#include <cuda_fp16.h>
#include <math.h>
#include <stdint.h>

#define B_    32
#define C_    64
#define F_    4096
#define N_    (B_ * F_)          // 131072 tokens
#define SIZE_ 2048
#define DECAY_ 0.99f
#define OMD_   0.01f
#define EPS_   1e-5f

// ---- output layout (concatenated tuple, all float32) ----
#define OFF_Q     0
#define OFF_IDX   8388608
#define OFF_LOSS  8519680
#define OFF_NEMB  8519681
#define OFF_NCS   8650753
#define OFF_NEA   8652801

// ---- device scratch ----
// codebook, fp16 hi/lo interleaved per k-pair: [code][32 pairs][2 u32]
__device__ uint32_t g_B16[SIZE_ * 64];
__device__ float g_e2h[SIZE_];       // 0.5 * ||e||^2 (fp32)
__device__ int   g_idx[N_];
__device__ float g_emb_sum[SIZE_ * C_];
__device__ float g_cs[SIZE_];
__device__ float g_inv[SIZE_];
__device__ float g_loss;

// ---- smem layout for the GEMM kernel (byte offsets) ----
// P0/P1 double as: (prologue) raw fp32 slab in P0, A fp16 layout in P1;
// (mainloop) B chunk double-buffers.
#define SM_P0   0                 // 128 rows x 288B
#define SM_P1   36864
#define SM_E2   73728             // 2048 f32 = 8192 B
#define SM_TOT  81920

__device__ __forceinline__ uint32_t smem_u32(const void* p) {
    uint32_t a;
    asm("{ .reg .u64 t; cvta.to.shared.u64 t, %1; cvt.u32.u64 %0, t; }"
        : "=r"(a) : "l"(p));
    return a;
}

__device__ __forceinline__ void cp_async16(uint32_t dst, const void* src) {
    asm volatile("cp.async.ca.shared.global [%0], [%1], 16;"
                 :: "r"(dst), "l"(src) : "memory");
}
#define CP_COMMIT() asm volatile("cp.async.commit_group;" ::: "memory")
#define CP_WAIT1()  asm volatile("cp.async.wait_group 1;"  ::: "memory")
#define CP_WAIT0()  asm volatile("cp.async.wait_group 0;"  ::: "memory")

__device__ __forceinline__ void mma16816(float c[4],
                                         uint32_t a0, uint32_t a1, uint32_t a2, uint32_t a3,
                                         uint32_t b0, uint32_t b1) {
    asm volatile(
        "mma.sync.aligned.m16n8k16.row.col.f32.f16.f16.f32 "
        "{%0,%1,%2,%3}, {%4,%5,%6,%7}, {%8,%9}, {%0,%1,%2,%3};"
        : "+f"(c[0]), "+f"(c[1]), "+f"(c[2]), "+f"(c[3])
        : "r"(a0), "r"(a1), "r"(a2), "r"(a3), "r"(b0), "r"(b1));
}

// ============================================================
// Kernel 0: codebook fp16 hi/lo split + 0.5||e||^2 + zero scratch
// ============================================================
__global__ void k_init(const float* __restrict__ embedding) {
    int i = blockIdx.x * blockDim.x + threadIdx.x;   // 0..131071
    int code = i >> 6;
    int c    = i & 63;
    if ((c & 1) == 0) {
        float e0 = embedding[i];
        float e1 = embedding[i + 1];
        __half h0 = __float2half_rn(e0);
        __half h1 = __float2half_rn(e1);
        __half l0 = __float2half_rn(e0 - __half2float(h0));
        __half l1 = __float2half_rn(e1 - __half2float(h1));
        __half2 hi = __halves2half2(h0, h1);   // low half = k even
        __half2 lo = __halves2half2(l0, l1);
        int pr = c >> 1;
        g_B16[code * 64 + pr * 2]     = *(uint32_t*)&hi;
        g_B16[code * 64 + pr * 2 + 1] = *(uint32_t*)&lo;
    }
    g_emb_sum[i] = 0.0f;
    if (i < SIZE_) {
        const float* er = embedding + i * C_;
        float s = 0.0f;
#pragma unroll
        for (int k = 0; k < C_; k++) s += er[k] * er[k];
        g_e2h[i] = 0.5f * s;
        g_cs[i] = 0.0f;
    }
    if (i == 0) g_loss = 0.0f;
}

// ============================================================
// Kernel 1: split-fp16 mma.sync distance GEMM + fused argmin
// CTA = 128 tokens, 256 threads (8 warps x 16 tokens).
// 16 chunks of 128 codes, cp.async double-buffered.
// 3 independent accumulator chains (hh/hl/lh) for MMA ILP.
// ============================================================
__global__ void __launch_bounds__(256, 2)
k_argmin_mma(const float* __restrict__ inputs) {
    extern __shared__ char sm[];
    uint32_t smb = smem_u32(sm);

    int tid = threadIdx.x;
    int w    = tid >> 5;
    int lane = tid & 31;
    int gid  = lane >> 2;
    int tig  = lane & 3;
    int b  = blockIdx.x >> 5;
    int f0 = (blockIdx.x & 31) << 7;

    // ---- stage raw fp32 slab [64 c][128 f] into P0 (coalesced) ----
    {
        const float4* inp4 = (const float4*)(inputs + (size_t)b * C_ * F_ + f0);
        float4* raw4 = (float4*)(sm + SM_P0);
#pragma unroll
        for (int it = tid; it < 2048; it += 256) {
            int c = it >> 5, m4 = it & 31;
            raw4[it] = inp4[c * (F_ / 4) + m4];
        }
    }
    // e2 table
    {
        const float4* src = (const float4*)g_e2h;
        float4* dst = (float4*)(sm + SM_E2);
#pragma unroll
        for (int it = tid; it < 512; it += 256) dst[it] = src[it];
    }
    __syncthreads();

    // ---- convert P0 raw -> P1 A fp16 hi/lo interleaved [m][pair][hi,lo] ----
    {
        const float* raw = (const float*)(sm + SM_P0);
#pragma unroll
        for (int it = tid; it < 4096; it += 256) {   // 128 m x 32 pairs
            int m = it & 127, j = it >> 7;
            float x0 = raw[(2 * j)     * 128 + m];
            float x1 = raw[(2 * j + 1) * 128 + m];
            __half h0 = __float2half_rn(x0);
            __half h1 = __float2half_rn(x1);
            __half l0 = __float2half_rn(x0 - __half2float(h0));
            __half l1 = __float2half_rn(x1 - __half2float(h1));
            __half2 hi = __halves2half2(h0, h1);
            __half2 lo = __halves2half2(l0, l1);
            uint2 v = {*(uint32_t*)&hi, *(uint32_t*)&lo};
            *(uint2*)(sm + SM_P1 + m * 288 + j * 8) = v;
        }
    }
    __syncthreads();

    // ---- load A fragments to registers (kept whole kernel) ----
    uint32_t ah[16], al[16];
#pragma unroll
    for (int s = 0; s < 4; s++) {
#pragma unroll
        for (int part = 0; part < 4; part++) {
            int m  = 16 * w + gid + (part & 1) * 8;
            int pr = 8 * s + tig + (part >> 1) * 4;
            uint2 v = *(const uint2*)(sm + SM_P1 + m * 288 + pr * 8);
            ah[s * 4 + part] = v.x;
            al[s * 4 + part] = v.y;
        }
    }
    __syncthreads();   // P0/P1 now free for the B pipeline

    // ---- prologue: cp.async B chunk 0 (->P0) and 1 (->P1) ----
    const char* gB = (const char*)g_B16;
#pragma unroll
    for (int r = 0; r < 8; r++) {
        int o = tid + 256 * r;            // 0..2047
        int row = o >> 4, g = o & 15;
        cp_async16(smb + SM_P0 + row * 288 + g * 16,
                   gB + (size_t)row * 256 + g * 16);
    }
    CP_COMMIT();
#pragma unroll
    for (int r = 0; r < 8; r++) {
        int o = tid + 256 * r;
        int row = o >> 4, g = o & 15;
        cp_async16(smb + SM_P1 + row * 288 + g * 16,
                   gB + (size_t)(128 + row) * 256 + g * 16);
    }
    CP_COMMIT();

    float bestv0 = 3.4e38f, bestv1 = 3.4e38f;
    int   besti0 = 0,       besti1 = 0;

#pragma unroll 1
    for (int i = 0; i < 16; i++) {
        if (i < 14) { CP_WAIT1(); } else { CP_WAIT0(); }
        __syncthreads();
        const char* buf = sm + ((i & 1) ? SM_P1 : SM_P0);

#pragma unroll
        for (int nt = 0; nt < 16; nt++) {
            int n = nt * 8 + gid;
            const char* base = buf + n * 288;
            uint32_t bh[8], bl[8];
#pragma unroll
            for (int s = 0; s < 4; s++) {
                uint2 v0 = *(const uint2*)(base + (8 * s + tig) * 8);
                uint2 v1 = *(const uint2*)(base + (8 * s + tig + 4) * 8);
                bh[s * 2]     = v0.x;  bl[s * 2]     = v0.y;
                bh[s * 2 + 1] = v1.x;  bl[s * 2 + 1] = v1.y;
            }
            // 3 independent accumulator chains (depth 4 each)
            float chh[4] = {0.f, 0.f, 0.f, 0.f};
            float chl[4] = {0.f, 0.f, 0.f, 0.f};
            float clh[4] = {0.f, 0.f, 0.f, 0.f};
#pragma unroll
            for (int s = 0; s < 4; s++) {
                mma16816(chh, ah[4*s], ah[4*s+1], ah[4*s+2], ah[4*s+3], bh[2*s], bh[2*s+1]);
                mma16816(chl, ah[4*s], ah[4*s+1], ah[4*s+2], ah[4*s+3], bl[2*s], bl[2*s+1]);
                mma16816(clh, al[4*s], al[4*s+1], al[4*s+2], al[4*s+3], bh[2*s], bh[2*s+1]);
            }

            int col = i * 128 + nt * 8 + 2 * tig;
            float2 e2v = *(const float2*)(sm + SM_E2 + col * 4);
            float s0 = e2v.x - ((chh[0] + chl[0]) + clh[0]);
            float s1 = e2v.y - ((chh[1] + chl[1]) + clh[1]);
            float s2 = e2v.x - ((chh[2] + chl[2]) + clh[2]);
            float s3 = e2v.y - ((chh[3] + chl[3]) + clh[3]);
            if (s0 < bestv0) { bestv0 = s0; besti0 = col; }
            if (s1 < bestv0) { bestv0 = s1; besti0 = col + 1; }
            if (s2 < bestv1) { bestv1 = s2; besti1 = col; }
            if (s3 < bestv1) { bestv1 = s3; besti1 = col + 1; }
        }
        __syncthreads();
        if (i < 14) {   // issue chunk i+2 into buf (i&1)
            uint32_t dstb = smb + ((i & 1) ? SM_P1 : SM_P0);
            size_t srcb = (size_t)(i + 2) * 128 * 256;
#pragma unroll
            for (int r = 0; r < 8; r++) {
                int o = tid + 256 * r;
                int row = o >> 4, g = o & 15;
                cp_async16(dstb + row * 288 + g * 16,
                           gB + srcb + (size_t)row * 256 + g * 16);
            }
            CP_COMMIT();
        }
    }

    // ---- cross-lane (quad) argmin reduce, then store ----
#pragma unroll
    for (int off = 1; off <= 2; off <<= 1) {
        float ov0 = __shfl_xor_sync(0xffffffffu, bestv0, off);
        int   oi0 = __shfl_xor_sync(0xffffffffu, besti0, off);
        float ov1 = __shfl_xor_sync(0xffffffffu, bestv1, off);
        int   oi1 = __shfl_xor_sync(0xffffffffu, besti1, off);
        if (ov0 < bestv0 || (ov0 == bestv0 && oi0 < besti0)) { bestv0 = ov0; besti0 = oi0; }
        if (ov1 < bestv1 || (ov1 == bestv1 && oi1 < besti1)) { bestv1 = ov1; besti1 = oi1; }
    }
    if (tig == 0) {
        int tok = b * F_ + f0 + w * 16 + gid;
        g_idx[tok]     = besti0;
        g_idx[tok + 8] = besti1;
    }
}

// ============================================================
// Kernel 2: gather quantized + scatter segment sums + loss
// ============================================================
__global__ void __launch_bounds__(128)
k_scatter(const float* __restrict__ inputs,
          const float* __restrict__ embedding,
          float* __restrict__ out) {
    __shared__ float xs[C_ * 128];
    float4* xs4 = (float4*)xs;

    int tid = threadIdx.x;
    int b  = blockIdx.x >> 5;
    int f0 = (blockIdx.x & 31) << 7;

    const float4* inp4 = (const float4*)(inputs + (size_t)b * C_ * F_);
    int f04 = f0 >> 2;
#pragma unroll
    for (int it = tid; it < 2048; it += 128) {
        int k = it >> 5, m4 = it & 31;
        xs4[it] = inp4[k * (F_ / 4) + f04 + m4];
    }
    __syncthreads();

    int t = b * F_ + f0 + tid;
    int idx = g_idx[t];
    const float4* e4 = (const float4*)(embedding + idx * C_);
    float* esum = g_emb_sum + (size_t)idx * C_;

    float lacc = 0.0f;
#pragma unroll
    for (int c4 = 0; c4 < 16; c4++) {
        float4 q = e4[c4];
        float qv[4] = {q.x, q.y, q.z, q.w};
#pragma unroll
        for (int l = 0; l < 4; l++) {
            int c = c4 * 4 + l;
            float x = xs[c * 128 + tid];
            float d = x - qv[l];
            lacc = fmaf(d, d, lacc);
            atomicAdd(&esum[c], x);
            xs[c * 128 + tid] = qv[l];
        }
    }
    atomicAdd(&g_cs[idx], 1.0f);
    out[OFF_IDX + t] = (float)idx;

#pragma unroll
    for (int off = 16; off > 0; off >>= 1)
        lacc += __shfl_down_sync(0xffffffffu, lacc, off);
    if ((tid & 31) == 0) atomicAdd(&g_loss, lacc);

    __syncthreads();
    float4* out4 = (float4*)(out + OFF_Q);
    size_t rowbase = (size_t)b * C_ * F_;
#pragma unroll
    for (int it = tid; it < 2048; it += 128) {
        int c = it >> 5, m4 = it & 31;
        out4[(rowbase + (size_t)c * F_ + f0) / 4 + m4] = xs4[it];
    }
}

// ============================================================
// Kernel 3: new_cluster_size, n, 1/smoothed, loss.  1 block.
// ============================================================
__global__ void __launch_bounds__(1024)
k_ema1(const float* __restrict__ cluster_size, float* __restrict__ out) {
    __shared__ float wsum[32];
    __shared__ float s_n;
    int tid = threadIdx.x;

    float ncs0 = DECAY_ * cluster_size[tid] + OMD_ * g_cs[tid];
    float ncs1 = DECAY_ * cluster_size[tid + 1024] + OMD_ * g_cs[tid + 1024];
    out[OFF_NCS + tid] = ncs0;
    out[OFF_NCS + tid + 1024] = ncs1;

    float s = ncs0 + ncs1;
#pragma unroll
    for (int off = 16; off > 0; off >>= 1)
        s += __shfl_down_sync(0xffffffffu, s, off);
    if ((tid & 31) == 0) wsum[tid >> 5] = s;
    __syncthreads();
    if (tid == 0) {
        float n = 0.0f;
#pragma unroll
        for (int w = 0; w < 32; w++) n += wsum[w];
        s_n = n;
        out[OFF_LOSS] = g_loss * (1.0f / (float)(N_ * C_));
    }
    __syncthreads();
    float n = s_n;
    float denom = n + (float)SIZE_ * EPS_;
    float mn = fmaxf(n, 1.0f);
    g_inv[tid]        = denom / ((ncs0 + EPS_) * mn);
    g_inv[tid + 1024] = denom / ((ncs1 + EPS_) * mn);
}

// ============================================================
// Kernel 4: new_embedding_avg and new_embedding.
// ============================================================
__global__ void __launch_bounds__(256)
k_ema2(const float* __restrict__ embedding_avg, float* __restrict__ out) {
    int i = blockIdx.x * 256 + threadIdx.x;
    int row = i >> 6;
    float nea = DECAY_ * embedding_avg[i] + OMD_ * g_emb_sum[i];
    out[OFF_NEA + i]  = nea;
    out[OFF_NEMB + i] = nea * g_inv[row];
}

// ============================================================
extern "C" void kernel_launch(void* const* d_in, const int* in_sizes, int n_in,
                              void* d_out, int out_size) {
    const float* inputs        = (const float*)d_in[0];
    const float* embedding     = (const float*)d_in[1];
    const float* embedding_avg = (const float*)d_in[2];
    const float* cluster_size  = (const float*)d_in[3];
    float* out = (float*)d_out;

    cudaFuncSetAttribute(k_argmin_mma, cudaFuncAttributeMaxDynamicSharedMemorySize, SM_TOT);

    k_init<<<512, 256>>>(embedding);
    k_argmin_mma<<<1024, 256, SM_TOT>>>(inputs);
    k_scatter<<<1024, 128>>>(inputs, embedding, out);
    k_ema1<<<1, 1024>>>(cluster_size, out);
    k_ema2<<<512, 256>>>(embedding_avg, out);
}